// round 1
// baseline (speedup 1.0000x reference)
#include <cuda_runtime.h>
#include <math.h>
#include <stdint.h>

#define BB 4
#define TT 16384
#define SSZ 8192
#define DD 256
#define GG 512
#define IN_DIM 771
#define MM (BB*TT)   /* 65536 rows */
#define KNN 8

// Scratch (static device arrays; no runtime allocation)
__device__ float g_x [(size_t)MM * IN_DIM];  // concat [tmpl(3) | local(256) | global(512)]
__device__ float g_h1[(size_t)MM * 256];
__device__ float g_h2[(size_t)MM * 256];
__device__ float g_m1[(size_t)MM * 128];
__device__ float g_m2[(size_t)MM * 64];

// ---------------------------------------------------------------------------
// Kernel 1: KNN (k=8) + gather/mean + build x rows
// Block: 256 threads, 256 template points. Surf processed in 2048-pt chunks
// staged in static smem (fits 48KB limit).
// ---------------------------------------------------------------------------
#define PPB 256
#define SCH 2048

__global__ void __launch_bounds__(256) knn_build_x(
    const float* __restrict__ tmpl, const float* __restrict__ surf,
    const float* __restrict__ gfeat, const float* __restrict__ pfeat)
{
    __shared__ float4 ssurf[SCH];          // 32 KB
    __shared__ int    sidx[PPB * KNN];     // 8 KB
    __shared__ float  sgf[GG];             // 2 KB

    const int b  = blockIdx.x / (TT / PPB);
    const int p0 = (blockIdx.x % (TT / PPB)) * PPB;
    const int tid = threadIdx.x;

    for (int i = tid; i < GG; i += 256) sgf[i] = gfeat[b * GG + i];

    const int pt = p0 + tid;
    const size_t trow = ((size_t)b * TT + pt) * 3;
    const float tx = tmpl[trow + 0], ty = tmpl[trow + 1], tz = tmpl[trow + 2];
    const float tsq = tx * tx + ty * ty + tz * tz;
    const float ntx = -2.f * tx, nty = -2.f * ty, ntz = -2.f * tz;

    float bd[KNN];
    int   bi[KNN];
#pragma unroll
    for (int i = 0; i < KNN; i++) { bd[i] = 3.4e38f; bi[i] = 0; }
    float wmax = 3.4e38f;
    int   wslot = 0;

    for (int c0 = 0; c0 < SSZ; c0 += SCH) {
        __syncthreads();
        for (int i = tid; i < SCH; i += 256) {
            size_t srow = ((size_t)b * SSZ + c0 + i) * 3;
            float sx = surf[srow], sy = surf[srow + 1], sz = surf[srow + 2];
            ssurf[i] = make_float4(sx, sy, sz, sx * sx + sy * sy + sz * sz);
        }
        __syncthreads();
#pragma unroll 4
        for (int s = 0; s < SCH; s++) {
            float4 v = ssurf[s];
            // same formula as reference: t_sq + s_sq - 2*dot
            float d2 = fmaf(ntx, v.x, fmaf(nty, v.y, fmaf(ntz, v.z, tsq + v.w)));
            if (d2 < wmax) {
#pragma unroll
                for (int i = 0; i < KNN; i++)
                    if (i == wslot) { bd[i] = d2; bi[i] = c0 + s; }
                wmax = -1.f;
#pragma unroll
                for (int i = 0; i < KNN; i++)
                    if (bd[i] > wmax) { wmax = bd[i]; wslot = i; }
            }
        }
    }

#pragma unroll
    for (int i = 0; i < KNN; i++) sidx[tid * KNN + i] = bi[i];
    __syncthreads();

    // Phase 2: cooperative gather + x-row assembly. 8 warps x 32 points.
    const int lane = tid & 31, wid = tid >> 5;
    for (int q = 0; q < PPB / 8; q++) {
        const int lp = wid * (PPB / 8) + q;
        float acc[8];
#pragma unroll
        for (int j = 0; j < 8; j++) acc[j] = 0.f;
#pragma unroll
        for (int n = 0; n < KNN; n++) {
            const int sI = sidx[lp * KNN + n];
            const float* row = pfeat + ((size_t)b * SSZ + sI) * DD;
#pragma unroll
            for (int j = 0; j < 8; j++) acc[j] += row[lane + 32 * j];
        }
        const size_t xbase = ((size_t)b * TT + p0 + lp) * IN_DIM;
#pragma unroll
        for (int j = 0; j < 8; j++)
            g_x[xbase + 3 + lane + 32 * j] = acc[j] * 0.125f;
#pragma unroll
        for (int j = 0; j < GG / 32; j++)
            g_x[xbase + 3 + DD + lane + 32 * j] = sgf[lane + 32 * j];
        if (lane < 3)
            g_x[xbase + lane] = tmpl[((size_t)b * TT + p0 + lp) * 3 + lane];
    }
}

// ---------------------------------------------------------------------------
// Kernel 2: SGEMM C = act(A[M,K] @ W[K,N] + bias). 64x64 tile, BK=16,
// 256 threads, 4x4 micro-tile per thread.
// ---------------------------------------------------------------------------
__global__ void __launch_bounds__(256) sgemm_bias(
    const float* __restrict__ A, const float* __restrict__ W,
    const float* __restrict__ bias, float* __restrict__ C,
    int M, int N, int K, int relu)
{
    __shared__ float As[64][17];                 // padded (bank spread)
    __shared__ __align__(16) float Bs[16][64];

    const int bm = blockIdx.y * 64, bn = blockIdx.x * 64;
    const int tid = threadIdx.x;
    const int txc = tid & 15, tyc = tid >> 4;

    float acc[4][4];
#pragma unroll
    for (int i = 0; i < 4; i++)
#pragma unroll
        for (int j = 0; j < 4; j++) acc[i][j] = 0.f;

    for (int k0 = 0; k0 < K; k0 += 16) {
        // A tile: 64 rows x 16 k; thread e -> (r=e>>4, c=e&15) coalesced 64B runs
#pragma unroll
        for (int i = 0; i < 4; i++) {
            int e = tid + i * 256;
            int r = e >> 4, c = e & 15;
            int gk = k0 + c;
            As[r][c] = (gk < K) ? A[(size_t)(bm + r) * K + gk] : 0.f;
        }
        // B tile: 16 k x 64 n
#pragma unroll
        for (int i = 0; i < 4; i++) {
            int e = tid + i * 256;
            int kr = e >> 6, c = e & 63;
            int gk = k0 + kr;
            Bs[kr][c] = (gk < K) ? W[(size_t)gk * N + bn + c] : 0.f;
        }
        __syncthreads();
#pragma unroll
        for (int kk = 0; kk < 16; kk++) {
            float a0 = As[tyc * 4 + 0][kk];
            float a1 = As[tyc * 4 + 1][kk];
            float a2 = As[tyc * 4 + 2][kk];
            float a3 = As[tyc * 4 + 3][kk];
            float4 bv = *(const float4*)&Bs[kk][txc * 4];
            acc[0][0] = fmaf(a0, bv.x, acc[0][0]);
            acc[0][1] = fmaf(a0, bv.y, acc[0][1]);
            acc[0][2] = fmaf(a0, bv.z, acc[0][2]);
            acc[0][3] = fmaf(a0, bv.w, acc[0][3]);
            acc[1][0] = fmaf(a1, bv.x, acc[1][0]);
            acc[1][1] = fmaf(a1, bv.y, acc[1][1]);
            acc[1][2] = fmaf(a1, bv.z, acc[1][2]);
            acc[1][3] = fmaf(a1, bv.w, acc[1][3]);
            acc[2][0] = fmaf(a2, bv.x, acc[2][0]);
            acc[2][1] = fmaf(a2, bv.y, acc[2][1]);
            acc[2][2] = fmaf(a2, bv.z, acc[2][2]);
            acc[2][3] = fmaf(a2, bv.w, acc[2][3]);
            acc[3][0] = fmaf(a3, bv.x, acc[3][0]);
            acc[3][1] = fmaf(a3, bv.y, acc[3][1]);
            acc[3][2] = fmaf(a3, bv.z, acc[3][2]);
            acc[3][3] = fmaf(a3, bv.w, acc[3][3]);
        }
        __syncthreads();
    }

#pragma unroll
    for (int i = 0; i < 4; i++) {
        const size_t crow = (size_t)(bm + tyc * 4 + i) * N + bn + txc * 4;
#pragma unroll
        for (int j = 0; j < 4; j++) {
            float v = acc[i][j] + bias[bn + txc * 4 + j];
            if (relu) v = fmaxf(v, 0.f);
            C[crow + j] = v;
        }
    }
}

// ---------------------------------------------------------------------------
// Head kernels: warp-per-row dot products
// ---------------------------------------------------------------------------
__global__ void __launch_bounds__(256) disp_head(
    const float* __restrict__ h2, const float* __restrict__ w,
    const float* __restrict__ b3, float* __restrict__ out)
{
    __shared__ float sw[256 * 3];
    const int tid = threadIdx.x;
    for (int i = tid; i < 768; i += 256) sw[i] = w[i];
    __syncthreads();
    const int lane = tid & 31, wid = tid >> 5;
    const int row = blockIdx.x * 8 + wid;
    const float* hr = h2 + (size_t)row * 256;
    float a0 = 0.f, a1 = 0.f, a2 = 0.f;
#pragma unroll
    for (int j = 0; j < 8; j++) {
        float h = hr[lane + 32 * j];
        a0 = fmaf(h, sw[(lane + 32 * j) * 3 + 0], a0);
        a1 = fmaf(h, sw[(lane + 32 * j) * 3 + 1], a1);
        a2 = fmaf(h, sw[(lane + 32 * j) * 3 + 2], a2);
    }
#pragma unroll
    for (int o = 16; o > 0; o >>= 1) {
        a0 += __shfl_down_sync(0xffffffffu, a0, o);
        a1 += __shfl_down_sync(0xffffffffu, a1, o);
        a2 += __shfl_down_sync(0xffffffffu, a2, o);
    }
    if (lane == 0) {
        out[(size_t)row * 3 + 0] = a0 + b3[0];
        out[(size_t)row * 3 + 1] = a1 + b3[1];
        out[(size_t)row * 3 + 2] = a2 + b3[2];
    }
}

__global__ void __launch_bounds__(256) mat_head(
    const float* __restrict__ m2, const float* __restrict__ w,
    const float* __restrict__ b, float* __restrict__ out)
{
    __shared__ float sw[64];
    const int tid = threadIdx.x;
    if (tid < 64) sw[tid] = w[tid];
    __syncthreads();
    const int lane = tid & 31, wid = tid >> 5;
    const int row = blockIdx.x * 8 + wid;
    const float* mr = m2 + (size_t)row * 64;
    float a = fmaf(mr[lane], sw[lane], mr[lane + 32] * sw[lane + 32]);
#pragma unroll
    for (int o = 16; o > 0; o >>= 1)
        a += __shfl_down_sync(0xffffffffu, a, o);
    if (lane == 0) {
        float z = a + b[0];
        out[row] = 1.f / (1.f + expf(-z));
    }
}

// ---------------------------------------------------------------------------
extern "C" void kernel_launch(void* const* d_in, const int* in_sizes, int n_in,
                              void* d_out, int out_size)
{
    const float* tmpl  = (const float*)d_in[0];
    const float* surf  = (const float*)d_in[1];
    const float* gfeat = (const float*)d_in[2];
    const float* pfeat = (const float*)d_in[3];
    const float* dw1 = (const float*)d_in[4];
    const float* db1 = (const float*)d_in[5];
    const float* dw2 = (const float*)d_in[6];
    const float* db2 = (const float*)d_in[7];
    const float* dw3 = (const float*)d_in[8];
    const float* db3 = (const float*)d_in[9];
    const float* mw1 = (const float*)d_in[10];
    const float* mb1 = (const float*)d_in[11];
    const float* mw2 = (const float*)d_in[12];
    const float* mb2 = (const float*)d_in[13];
    const float* mw3 = (const float*)d_in[14];
    const float* mb3 = (const float*)d_in[15];
    float* out = (float*)d_out;

    float *x, *h1, *h2, *m1, *m2;
    cudaGetSymbolAddress((void**)&x,  g_x);
    cudaGetSymbolAddress((void**)&h1, g_h1);
    cudaGetSymbolAddress((void**)&h2, g_h2);
    cudaGetSymbolAddress((void**)&m1, g_m1);
    cudaGetSymbolAddress((void**)&m2, g_m2);

    // 1) KNN + local feature + x assembly
    knn_build_x<<<MM / PPB, 256>>>(tmpl, surf, gfeat, pfeat);

    // 2) disp head MLP
    sgemm_bias<<<dim3(256 / 64, MM / 64), 256>>>(x,  dw1, db1, h1, MM, 256, IN_DIM, 1);
    sgemm_bias<<<dim3(256 / 64, MM / 64), 256>>>(h1, dw2, db2, h2, MM, 256, 256,    1);
    disp_head<<<MM / 8, 256>>>(h2, dw3, db3, out);

    // 3) material head MLP
    sgemm_bias<<<dim3(128 / 64, MM / 64), 256>>>(x,  mw1, mb1, m1, MM, 128, IN_DIM, 1);
    sgemm_bias<<<dim3(64 / 64,  MM / 64), 256>>>(m1, mw2, mb2, m2, MM, 64,  128,    1);
    mat_head<<<MM / 8, 256>>>(m2, mw3, mb3, out + (size_t)MM * 3);
}

// round 3
// speedup vs baseline: 1.8767x; 1.8767x over previous
#include <cuda_runtime.h>
#include <cuda_bf16.h>
#include <math.h>
#include <stdint.h>

#define BB 4
#define TT 16384
#define SSZ 8192
#define DD 256
#define GG 512
#define IN_DIM 771
#define X_STRIDE 832            /* IN_DIM padded to multiple of 64 */
#define MM (BB*TT)              /* 65536 rows */
#define KNN 8

// tcgen05 is an arch-SPECIFIC feature: only emit it in the sm_103a/sm_100a
// device pass. The compute_103 PTX-fallback pass gets an empty stub (never
// executed at runtime — the exact-match cubin is used).
#if defined(__CUDA_ARCH_FEAT_SM103_ALL) || defined(__CUDA_ARCH_FEAT_SM100_ALL) || \
    defined(__CUDA_ARCH_FEAT_SM101_ALL) || defined(__CUDA_ARCH_SPECIFIC__)
#define TC_ENABLED 1
#else
#define TC_ENABLED 0
#endif

// ---------------------------------------------------------------------------
// Static device scratch (no runtime allocation)
// ---------------------------------------------------------------------------
__device__ float g_x [(size_t)MM * X_STRIDE];   // [tmpl3 | local256 | global512 | pad61=0]
__device__ float g_h1[(size_t)MM * 256];
__device__ float g_h2[(size_t)MM * 256];
__device__ float g_m1[(size_t)MM * 128];
__device__ float g_m2[(size_t)MM * 64];

// Repacked transposed weights, bf16 hi/lo, K padded: Bt[n*Kpad + k]
__device__ __nv_bfloat16 g_dw1h[256 * 832], g_dw1l[256 * 832];
__device__ __nv_bfloat16 g_dw2h[256 * 256], g_dw2l[256 * 256];
__device__ __nv_bfloat16 g_mw1h[128 * 832], g_mw1l[128 * 832];
__device__ __nv_bfloat16 g_mw2h[64 * 128],  g_mw2l[64 * 128];

// ---------------------------------------------------------------------------
// PTX helpers
// ---------------------------------------------------------------------------
__device__ __forceinline__ uint32_t smem_u32(const void* p) {
    uint32_t a;
    asm("{ .reg .u64 t; cvta.to.shared.u64 t, %1; cvt.u32.u64 %0, t; }" : "=r"(a) : "l"(p));
    return a;
}
__device__ __forceinline__ uint32_t elect_one_pred() {
    uint32_t p;
    asm volatile("{ .reg .pred p; elect.sync _|p, 0xFFFFFFFF; selp.b32 %0, 1, 0, p; }" : "=r"(p));
    return p;
}
#define SWZ128(x) ((x) ^ (((x) >> 3) & 0x70))

static __device__ constexpr uint64_t SMEM_DESC_BASE_SW128 =
    (uint64_t(2) << 61) | (uint64_t(1) << 46) | (uint64_t(64) << 32) | (uint64_t(1) << 16);
#define MAKE_DESC(addr) (SMEM_DESC_BASE_SW128 | ((uint64_t)((addr) >> 4) & 0x3FFF))

#if TC_ENABLED
#define TC_ALLOC(sm, n)  asm volatile("tcgen05.alloc.cta_group::1.sync.aligned.shared::cta.b32 [%0], %1;" :: "r"((uint32_t)(sm)), "r"((uint32_t)(n)) : "memory")
#define TC_DEALLOC(t, n) asm volatile("tcgen05.dealloc.cta_group::1.sync.aligned.b32 %0, %1;" :: "r"(t), "r"((uint32_t)(n)))
#define TC_RELINQ()      asm volatile("tcgen05.relinquish_alloc_permit.cta_group::1.sync.aligned;")
#define TC_COMMIT(mb)    asm volatile("tcgen05.commit.cta_group::1.mbarrier::arrive::one.shared::cluster.b64 [%0];" :: "r"((uint32_t)(mb)) : "memory")
#define TC_FENCE_AFTER() asm volatile("tcgen05.fence::after_thread_sync;" ::: "memory")
#define TC_WAIT_LD()     asm volatile("tcgen05.wait::ld.sync.aligned;" ::: "memory")
#else
#define TC_ALLOC(sm, n)
#define TC_DEALLOC(t, n)
#define TC_RELINQ()
#define TC_COMMIT(mb)
#define TC_FENCE_AFTER()
#define TC_WAIT_LD()
#endif

#define FENCE_ASYNC()    asm volatile("fence.proxy.async.shared::cta;" ::: "memory")
#define MBAR_INIT(mb, c) asm volatile("mbarrier.init.shared.b64 [%0], %1;" :: "r"((uint32_t)(mb)), "r"((uint32_t)(c)) : "memory")

__device__ __forceinline__ void mbar_wait(uint32_t mb, uint32_t parity) {
    uint32_t done;
    asm volatile(
        "{ .reg .pred p; mbarrier.try_wait.parity.acquire.cta.shared::cta.b64 p, [%1], %2; selp.b32 %0, 1, 0, p; }"
        : "=r"(done) : "r"(mb), "r"(parity) : "memory");
    if (!done) {
        asm volatile(
            "{ .reg .pred P1;\n"
            "W%=: mbarrier.try_wait.parity.acquire.cta.shared::cta.b64 P1, [%0], %1, 0x989680;\n"
            "@P1 bra.uni D%=;\n bra.uni W%=;\n D%=: }"
            :: "r"(mb), "r"(parity) : "memory");
    }
}

__device__ __forceinline__ void mma_f16_ss(uint32_t d, uint64_t a, uint64_t b,
                                           uint32_t idesc, uint32_t en) {
#if TC_ENABLED
    asm volatile(
        "{ .reg .pred p; setp.ne.u32 p, %4, 0;\n"
        "tcgen05.mma.cta_group::1.kind::f16 [%0], %1, %2, %3, {%5,%5,%5,%5}, p; }"
        :: "r"(d), "l"(a), "l"(b), "r"(idesc), "r"(en), "r"(0u) : "memory");
#endif
}

__device__ __forceinline__ void tc_ld_x32(uint32_t* r, uint32_t addr) {
#if TC_ENABLED
    asm volatile("tcgen05.ld.sync.aligned.32x32b.x32.b32 "
        "{%0,%1,%2,%3,%4,%5,%6,%7,%8,%9,%10,%11,%12,%13,%14,%15,"
        "%16,%17,%18,%19,%20,%21,%22,%23,%24,%25,%26,%27,%28,%29,%30,%31}, [%32];"
        : "=r"(r[0]),"=r"(r[1]),"=r"(r[2]),"=r"(r[3]),"=r"(r[4]),"=r"(r[5]),"=r"(r[6]),"=r"(r[7]),
          "=r"(r[8]),"=r"(r[9]),"=r"(r[10]),"=r"(r[11]),"=r"(r[12]),"=r"(r[13]),"=r"(r[14]),"=r"(r[15]),
          "=r"(r[16]),"=r"(r[17]),"=r"(r[18]),"=r"(r[19]),"=r"(r[20]),"=r"(r[21]),"=r"(r[22]),"=r"(r[23]),
          "=r"(r[24]),"=r"(r[25]),"=r"(r[26]),"=r"(r[27]),"=r"(r[28]),"=r"(r[29]),"=r"(r[30]),"=r"(r[31])
        : "r"(addr));
#endif
}

// ---------------------------------------------------------------------------
// Kernel 1: KNN (k=8) + gather/mean + build padded x rows
// ---------------------------------------------------------------------------
#define PPB 256
#define SCH 2048

__global__ void __launch_bounds__(256) knn_build_x(
    const float* __restrict__ tmpl, const float* __restrict__ surf,
    const float* __restrict__ gfeat, const float* __restrict__ pfeat)
{
    __shared__ float4 ssurf[SCH];
    __shared__ int    sidx[PPB * KNN];
    __shared__ float  sgf[GG];

    const int b  = blockIdx.x / (TT / PPB);
    const int p0 = (blockIdx.x % (TT / PPB)) * PPB;
    const int tid = threadIdx.x;

    for (int i = tid; i < GG; i += 256) sgf[i] = gfeat[b * GG + i];

    const int pt = p0 + tid;
    const size_t trow = ((size_t)b * TT + pt) * 3;
    const float tx = tmpl[trow + 0], ty = tmpl[trow + 1], tz = tmpl[trow + 2];
    const float tsq = tx * tx + ty * ty + tz * tz;
    const float ntx = -2.f * tx, nty = -2.f * ty, ntz = -2.f * tz;

    float bd[KNN]; int bi[KNN];
#pragma unroll
    for (int i = 0; i < KNN; i++) { bd[i] = 3.4e38f; bi[i] = 0; }
    float wmax = 3.4e38f; int wslot = 0;

    for (int c0 = 0; c0 < SSZ; c0 += SCH) {
        __syncthreads();
        for (int i = tid; i < SCH; i += 256) {
            size_t srow = ((size_t)b * SSZ + c0 + i) * 3;
            float sx = surf[srow], sy = surf[srow + 1], sz = surf[srow + 2];
            ssurf[i] = make_float4(sx, sy, sz, sx * sx + sy * sy + sz * sz);
        }
        __syncthreads();
#pragma unroll 4
        for (int s = 0; s < SCH; s++) {
            float4 v = ssurf[s];
            float d2 = fmaf(ntx, v.x, fmaf(nty, v.y, fmaf(ntz, v.z, tsq + v.w)));
            if (d2 < wmax) {
#pragma unroll
                for (int i = 0; i < KNN; i++)
                    if (i == wslot) { bd[i] = d2; bi[i] = c0 + s; }
                wmax = -1.f;
#pragma unroll
                for (int i = 0; i < KNN; i++)
                    if (bd[i] > wmax) { wmax = bd[i]; wslot = i; }
            }
        }
    }

#pragma unroll
    for (int i = 0; i < KNN; i++) sidx[tid * KNN + i] = bi[i];
    __syncthreads();

    const int lane = tid & 31, wid = tid >> 5;
    for (int q = 0; q < PPB / 8; q++) {
        const int lp = wid * (PPB / 8) + q;
        float acc[8];
#pragma unroll
        for (int j = 0; j < 8; j++) acc[j] = 0.f;
#pragma unroll
        for (int n = 0; n < KNN; n++) {
            const int sI = sidx[lp * KNN + n];
            const float* row = pfeat + ((size_t)b * SSZ + sI) * DD;
#pragma unroll
            for (int j = 0; j < 8; j++) acc[j] += row[lane + 32 * j];
        }
        const size_t xbase = ((size_t)b * TT + p0 + lp) * X_STRIDE;
#pragma unroll
        for (int j = 0; j < 8; j++)
            g_x[xbase + 3 + lane + 32 * j] = acc[j] * 0.125f;
#pragma unroll
        for (int j = 0; j < GG / 32; j++)
            g_x[xbase + 3 + DD + lane + 32 * j] = sgf[lane + 32 * j];
        if (lane < 3)
            g_x[xbase + lane] = tmpl[((size_t)b * TT + p0 + lp) * 3 + lane];
        // zero pad cols 771..831
        g_x[xbase + IN_DIM + lane] = 0.f;
        if (lane < 29) g_x[xbase + IN_DIM + 32 + lane] = 0.f;
    }
}

// ---------------------------------------------------------------------------
// Weight repack: W[K,N] fp32 -> Bt hi/lo bf16 [N, Kpad] (zero-padded K)
// ---------------------------------------------------------------------------
__global__ void repack_w(const float* __restrict__ W, __nv_bfloat16* __restrict__ hi,
                         __nv_bfloat16* __restrict__ lo, int K, int N, int Kpad)
{
    int idx = blockIdx.x * 256 + threadIdx.x;
    if (idx >= N * Kpad) return;
    int n = idx / Kpad, k = idx - n * Kpad;
    float v = (k < K) ? W[(size_t)k * N + n] : 0.f;
    __nv_bfloat16 h = __float2bfloat16(v);
    hi[idx] = h;
    lo[idx] = __float2bfloat16(v - __bfloat162float(h));
}

// ---------------------------------------------------------------------------
// tcgen05 GEMM: C[M,NT] = act(A[M,K] @ Bt^T + bias), split-bf16 (3 MMAs)
// CTA: 128 rows, full NT cols. K in chunks of 64 (4 K16-steps).
// ---------------------------------------------------------------------------
template<int NT>
__global__ void __launch_bounds__(256) gemm_tc(
    const float* __restrict__ A, int Astride, int kchunks,
    const __nv_bfloat16* __restrict__ Bth, const __nv_bfloat16* __restrict__ Btl,
    int Kpad, const float* __restrict__ bias, float* __restrict__ C, int relu)
{
#if TC_ENABLED
    extern __shared__ __align__(1024) char smem[];
    constexpr int A_HI = 0, A_LO = 16384, B_HI = 32768;

    __shared__ uint32_t s_tmem;
    __shared__ __align__(8) uint64_t s_mbar;
    __shared__ float sb[NT];

    const uint32_t smb = smem_u32(smem);
    const uint32_t mbar = smem_u32(&s_mbar);
    const int tid = threadIdx.x, wid = tid >> 5, lane = tid & 31;
    const int bm = blockIdx.x * 128;

    if (tid < NT) sb[tid] = bias[tid];
    if (wid == 0) { TC_ALLOC(smem_u32(&s_tmem), NT); TC_RELINQ(); }
    if (tid == 0) MBAR_INIT(mbar, 1);
    __syncthreads();
    uint32_t tmem;
    asm volatile("ld.shared.b32 %0, [%1];" : "=r"(tmem) : "r"(smem_u32(&s_tmem)));

    const uint32_t idesc = (1u << 4) | (1u << 7) | (1u << 10) | ((NT / 8) << 17) | (8u << 24);

    for (int ch = 0; ch < kchunks; ch++) {
        // stage A chunk: 128 rows x 64 fp32 -> bf16 hi/lo, SW128
        for (int u = tid; u < 1024; u += 256) {
            int r = u >> 3, c8 = u & 7;
            const float* src = A + (size_t)(bm + r) * Astride + (size_t)ch * 64 + c8 * 8;
            float4 v0 = *(const float4*)src;
            float4 v1 = *(const float4*)(src + 4);
            float a[8] = {v0.x, v0.y, v0.z, v0.w, v1.x, v1.y, v1.z, v1.w};
            __align__(16) __nv_bfloat16 h[8], l[8];
#pragma unroll
            for (int j = 0; j < 8; j++) {
                h[j] = __float2bfloat16(a[j]);
                l[j] = __float2bfloat16(a[j] - __bfloat162float(h[j]));
            }
            uint32_t off = SWZ128((uint32_t)(r * 128 + c8 * 16));
            *(uint4*)(smem + A_HI + off) = *(const uint4*)h;
            *(uint4*)(smem + A_LO + off) = *(const uint4*)l;
        }
        // stage B chunk: NT rows x 64 bf16 (hi/lo), SW128
        for (int u = tid; u < NT * 8; u += 256) {
            int r = u >> 3, c8 = u & 7;
            size_t g = (size_t)r * Kpad + (size_t)ch * 64 + c8 * 8;
            uint4 vh = *(const uint4*)(Bth + g);
            uint4 vl = *(const uint4*)(Btl + g);
            uint32_t off = SWZ128((uint32_t)(r * 128 + c8 * 16));
            *(uint4*)(smem + B_HI + off) = vh;
            *(uint4*)(smem + B_HI + NT * 128 + off) = vl;
        }
        __syncthreads();

        if (wid == 0 && elect_one_pred()) {
            FENCE_ASYNC();
            uint64_t ah = MAKE_DESC(smb + A_HI), al = MAKE_DESC(smb + A_LO);
            uint64_t bh = MAKE_DESC(smb + B_HI), bl = MAKE_DESC(smb + B_HI + NT * 128);
#pragma unroll
            for (int ks = 0; ks < 4; ks++) {
                uint32_t en0 = (ch == 0 && ks == 0) ? 0u : 1u;
                mma_f16_ss(tmem, ah + ks * 2, bh + ks * 2, idesc, en0);
                mma_f16_ss(tmem, ah + ks * 2, bl + ks * 2, idesc, 1u);
                mma_f16_ss(tmem, al + ks * 2, bh + ks * 2, idesc, 1u);
            }
            TC_COMMIT(mbar);
        }
        mbar_wait(mbar, (uint32_t)(ch & 1));
        __syncthreads();
    }

    TC_FENCE_AFTER();
    if (wid < 4) {
        const size_t row = bm + wid * 32 + lane;
#pragma unroll
        for (int c0 = 0; c0 < NT; c0 += 32) {
            uint32_t r[32];
            tc_ld_x32(r, tmem + c0);
            TC_WAIT_LD();
#pragma unroll
            for (int j4 = 0; j4 < 8; j4++) {
                float v0 = __uint_as_float(r[j4 * 4 + 0]) + sb[c0 + j4 * 4 + 0];
                float v1 = __uint_as_float(r[j4 * 4 + 1]) + sb[c0 + j4 * 4 + 1];
                float v2 = __uint_as_float(r[j4 * 4 + 2]) + sb[c0 + j4 * 4 + 2];
                float v3 = __uint_as_float(r[j4 * 4 + 3]) + sb[c0 + j4 * 4 + 3];
                if (relu) {
                    v0 = fmaxf(v0, 0.f); v1 = fmaxf(v1, 0.f);
                    v2 = fmaxf(v2, 0.f); v3 = fmaxf(v3, 0.f);
                }
                *(float4*)(C + row * NT + c0 + j4 * 4) = make_float4(v0, v1, v2, v3);
            }
        }
    }
    __syncthreads();
    if (wid == 0) TC_DEALLOC(tmem, NT);
#endif  // TC_ENABLED
}

// ---------------------------------------------------------------------------
// Head kernels
// ---------------------------------------------------------------------------
__global__ void __launch_bounds__(256) disp_head(
    const float* __restrict__ h2, const float* __restrict__ w,
    const float* __restrict__ b3, float* __restrict__ out)
{
    __shared__ float sw[256 * 3];
    const int tid = threadIdx.x;
    for (int i = tid; i < 768; i += 256) sw[i] = w[i];
    __syncthreads();
    const int lane = tid & 31, wid = tid >> 5;
    const int row = blockIdx.x * 8 + wid;
    const float* hr = h2 + (size_t)row * 256;
    float a0 = 0.f, a1 = 0.f, a2 = 0.f;
#pragma unroll
    for (int j = 0; j < 8; j++) {
        float h = hr[lane + 32 * j];
        a0 = fmaf(h, sw[(lane + 32 * j) * 3 + 0], a0);
        a1 = fmaf(h, sw[(lane + 32 * j) * 3 + 1], a1);
        a2 = fmaf(h, sw[(lane + 32 * j) * 3 + 2], a2);
    }
#pragma unroll
    for (int o = 16; o > 0; o >>= 1) {
        a0 += __shfl_down_sync(0xffffffffu, a0, o);
        a1 += __shfl_down_sync(0xffffffffu, a1, o);
        a2 += __shfl_down_sync(0xffffffffu, a2, o);
    }
    if (lane == 0) {
        out[(size_t)row * 3 + 0] = a0 + b3[0];
        out[(size_t)row * 3 + 1] = a1 + b3[1];
        out[(size_t)row * 3 + 2] = a2 + b3[2];
    }
}

__global__ void __launch_bounds__(256) mat_head(
    const float* __restrict__ m2, const float* __restrict__ w,
    const float* __restrict__ b, float* __restrict__ out)
{
    __shared__ float sw[64];
    const int tid = threadIdx.x;
    if (tid < 64) sw[tid] = w[tid];
    __syncthreads();
    const int lane = tid & 31, wid = tid >> 5;
    const int row = blockIdx.x * 8 + wid;
    const float* mr = m2 + (size_t)row * 64;
    float a = fmaf(mr[lane], sw[lane], mr[lane + 32] * sw[lane + 32]);
#pragma unroll
    for (int o = 16; o > 0; o >>= 1)
        a += __shfl_down_sync(0xffffffffu, a, o);
    if (lane == 0) {
        float z = a + b[0];
        out[row] = 1.f / (1.f + expf(-z));
    }
}

// ---------------------------------------------------------------------------
extern "C" void kernel_launch(void* const* d_in, const int* in_sizes, int n_in,
                              void* d_out, int out_size)
{
    const float* tmpl  = (const float*)d_in[0];
    const float* surf  = (const float*)d_in[1];
    const float* gfeat = (const float*)d_in[2];
    const float* pfeat = (const float*)d_in[3];
    const float* dw1 = (const float*)d_in[4];
    const float* db1 = (const float*)d_in[5];
    const float* dw2 = (const float*)d_in[6];
    const float* db2 = (const float*)d_in[7];
    const float* dw3 = (const float*)d_in[8];
    const float* db3 = (const float*)d_in[9];
    const float* mw1 = (const float*)d_in[10];
    const float* mb1 = (const float*)d_in[11];
    const float* mw2 = (const float*)d_in[12];
    const float* mb2 = (const float*)d_in[13];
    const float* mw3 = (const float*)d_in[14];
    const float* mb3 = (const float*)d_in[15];
    float* out = (float*)d_out;

    float *x, *h1, *h2, *m1, *m2;
    cudaGetSymbolAddress((void**)&x,  g_x);
    cudaGetSymbolAddress((void**)&h1, g_h1);
    cudaGetSymbolAddress((void**)&h2, g_h2);
    cudaGetSymbolAddress((void**)&m1, g_m1);
    cudaGetSymbolAddress((void**)&m2, g_m2);
    __nv_bfloat16 *dw1h, *dw1l, *dw2h, *dw2l, *mw1h, *mw1l, *mw2h, *mw2l;
    cudaGetSymbolAddress((void**)&dw1h, g_dw1h);
    cudaGetSymbolAddress((void**)&dw1l, g_dw1l);
    cudaGetSymbolAddress((void**)&dw2h, g_dw2h);
    cudaGetSymbolAddress((void**)&dw2l, g_dw2l);
    cudaGetSymbolAddress((void**)&mw1h, g_mw1h);
    cudaGetSymbolAddress((void**)&mw1l, g_mw1l);
    cudaGetSymbolAddress((void**)&mw2h, g_mw2h);
    cudaGetSymbolAddress((void**)&mw2l, g_mw2l);

    cudaFuncSetAttribute(gemm_tc<256>, cudaFuncAttributeMaxDynamicSharedMemorySize, 32768 + 256 * 256);
    cudaFuncSetAttribute(gemm_tc<128>, cudaFuncAttributeMaxDynamicSharedMemorySize, 32768 + 128 * 256);
    cudaFuncSetAttribute(gemm_tc<64>,  cudaFuncAttributeMaxDynamicSharedMemorySize, 32768 + 64 * 256);

    // 1) KNN + local feature + padded x assembly
    knn_build_x<<<MM / PPB, 256>>>(tmpl, surf, gfeat, pfeat);

    // 2) weight repack (tiny)
    repack_w<<<(256 * 832 + 255) / 256, 256>>>(dw1, dw1h, dw1l, IN_DIM, 256, 832);
    repack_w<<<(256 * 256 + 255) / 256, 256>>>(dw2, dw2h, dw2l, 256, 256, 256);
    repack_w<<<(128 * 832 + 255) / 256, 256>>>(mw1, mw1h, mw1l, IN_DIM, 128, 832);
    repack_w<<<(64 * 128 + 255) / 256, 256>>>(mw2, mw2h, mw2l, 128, 64, 128);

    // 3) tcgen05 GEMMs
    gemm_tc<256><<<MM / 128, 256, 32768 + 256 * 256>>>(x,  X_STRIDE, 13, dw1h, dw1l, 832, db1, h1, 1);
    gemm_tc<256><<<MM / 128, 256, 32768 + 256 * 256>>>(h1, 256,      4,  dw2h, dw2l, 256, db2, h2, 1);
    gemm_tc<128><<<MM / 128, 256, 32768 + 128 * 256>>>(x,  X_STRIDE, 13, mw1h, mw1l, 832, mb1, m1, 1);
    gemm_tc<64> <<<MM / 128, 256, 32768 + 64  * 256>>>(m1, 128,      2,  mw2h, mw2l, 128, mb2, m2, 1);

    // 4) heads
    disp_head<<<MM / 8, 256>>>(h2, dw3, db3, out);
    mat_head<<<MM / 8, 256>>>(m2, mw3, mb3, out + (size_t)MM * 3);
}

// round 4
// speedup vs baseline: 2.0254x; 1.0793x over previous
#include <cuda_runtime.h>
#include <cuda_bf16.h>
#include <math.h>
#include <stdint.h>

#define BB 4
#define TT 16384
#define SSZ 8192
#define DD 256
#define GG 512
#define KX 259                  /* tmpl(3) + local(256); global folded into bias */
#define X_STRIDE 320            /* KX padded to multiple of 64 */
#define MM (BB*TT)              /* 65536 rows */
#define KNN 8

// tcgen05 is arch-specific: only emit in the sm_103a/sm_100a cubin pass.
#if defined(__CUDA_ARCH_FEAT_SM103_ALL) || defined(__CUDA_ARCH_FEAT_SM100_ALL) || \
    defined(__CUDA_ARCH_FEAT_SM101_ALL) || defined(__CUDA_ARCH_SPECIFIC__)
#define TC_ENABLED 1
#else
#define TC_ENABLED 0
#endif

// ---------------------------------------------------------------------------
// Static device scratch
// ---------------------------------------------------------------------------
__device__ float g_x [(size_t)MM * X_STRIDE];   // [tmpl3 | local256 | pad61=0]
__device__ float g_h1[(size_t)MM * 256];
__device__ float g_h2[(size_t)MM * 256];
__device__ float g_m1[(size_t)MM * 128];
__device__ float g_m2[(size_t)MM * 64];

// Repacked transposed weights, bf16 hi/lo, K padded: Bt[n*Kpad + k]
__device__ __nv_bfloat16 g_dw1h[256 * 320], g_dw1l[256 * 320];
__device__ __nv_bfloat16 g_dw2h[256 * 256], g_dw2l[256 * 256];
__device__ __nv_bfloat16 g_mw1h[128 * 320], g_mw1l[128 * 320];
__device__ __nv_bfloat16 g_mw2h[64 * 128],  g_mw2l[64 * 128];

// Per-batch folded biases: db + gfeat[b] @ W[259:771]
__device__ float g_gbd[4 * 256];
__device__ float g_gbm[4 * 128];

// ---------------------------------------------------------------------------
// PTX helpers
// ---------------------------------------------------------------------------
__device__ __forceinline__ uint32_t smem_u32(const void* p) {
    uint32_t a;
    asm("{ .reg .u64 t; cvta.to.shared.u64 t, %1; cvt.u32.u64 %0, t; }" : "=r"(a) : "l"(p));
    return a;
}
__device__ __forceinline__ uint32_t elect_one_pred() {
    uint32_t p;
    asm volatile("{ .reg .pred p; elect.sync _|p, 0xFFFFFFFF; selp.b32 %0, 1, 0, p; }" : "=r"(p));
    return p;
}
#define SWZ128(x) ((x) ^ (((x) >> 3) & 0x70))

static __device__ constexpr uint64_t SMEM_DESC_BASE_SW128 =
    (uint64_t(2) << 61) | (uint64_t(1) << 46) | (uint64_t(64) << 32) | (uint64_t(1) << 16);
#define MAKE_DESC(addr) (SMEM_DESC_BASE_SW128 | ((uint64_t)((addr) >> 4) & 0x3FFF))

#if TC_ENABLED
#define TC_ALLOC(sm, n)  asm volatile("tcgen05.alloc.cta_group::1.sync.aligned.shared::cta.b32 [%0], %1;" :: "r"((uint32_t)(sm)), "r"((uint32_t)(n)) : "memory")
#define TC_DEALLOC(t, n) asm volatile("tcgen05.dealloc.cta_group::1.sync.aligned.b32 %0, %1;" :: "r"(t), "r"((uint32_t)(n)))
#define TC_RELINQ()      asm volatile("tcgen05.relinquish_alloc_permit.cta_group::1.sync.aligned;")
#define TC_COMMIT(mb)    asm volatile("tcgen05.commit.cta_group::1.mbarrier::arrive::one.shared::cluster.b64 [%0];" :: "r"((uint32_t)(mb)) : "memory")
#define TC_FENCE_AFTER() asm volatile("tcgen05.fence::after_thread_sync;" ::: "memory")
#define TC_WAIT_LD()     asm volatile("tcgen05.wait::ld.sync.aligned;" ::: "memory")
#else
#define TC_ALLOC(sm, n)
#define TC_DEALLOC(t, n)
#define TC_RELINQ()
#define TC_COMMIT(mb)
#define TC_FENCE_AFTER()
#define TC_WAIT_LD()
#endif

#define FENCE_ASYNC()    asm volatile("fence.proxy.async.shared::cta;" ::: "memory")
#define MBAR_INIT(mb, c) asm volatile("mbarrier.init.shared.b64 [%0], %1;" :: "r"((uint32_t)(mb)), "r"((uint32_t)(c)) : "memory")

__device__ __forceinline__ void mbar_wait(uint32_t mb, uint32_t parity) {
    uint32_t done;
    asm volatile(
        "{ .reg .pred p; mbarrier.try_wait.parity.acquire.cta.shared::cta.b64 p, [%1], %2; selp.b32 %0, 1, 0, p; }"
        : "=r"(done) : "r"(mb), "r"(parity) : "memory");
    if (!done) {
        asm volatile(
            "{ .reg .pred P1;\n"
            "W%=: mbarrier.try_wait.parity.acquire.cta.shared::cta.b64 P1, [%0], %1, 0x989680;\n"
            "@P1 bra.uni D%=;\n bra.uni W%=;\n D%=: }"
            :: "r"(mb), "r"(parity) : "memory");
    }
}

__device__ __forceinline__ void mma_f16_ss(uint32_t d, uint64_t a, uint64_t b,
                                           uint32_t idesc, uint32_t en) {
#if TC_ENABLED
    asm volatile(
        "{ .reg .pred p; setp.ne.u32 p, %4, 0;\n"
        "tcgen05.mma.cta_group::1.kind::f16 [%0], %1, %2, %3, {%5,%5,%5,%5}, p; }"
        :: "r"(d), "l"(a), "l"(b), "r"(idesc), "r"(en), "r"(0u) : "memory");
#endif
}

__device__ __forceinline__ void tc_ld_x32(uint32_t* r, uint32_t addr) {
#if TC_ENABLED
    asm volatile("tcgen05.ld.sync.aligned.32x32b.x32.b32 "
        "{%0,%1,%2,%3,%4,%5,%6,%7,%8,%9,%10,%11,%12,%13,%14,%15,"
        "%16,%17,%18,%19,%20,%21,%22,%23,%24,%25,%26,%27,%28,%29,%30,%31}, [%32];"
        : "=r"(r[0]),"=r"(r[1]),"=r"(r[2]),"=r"(r[3]),"=r"(r[4]),"=r"(r[5]),"=r"(r[6]),"=r"(r[7]),
          "=r"(r[8]),"=r"(r[9]),"=r"(r[10]),"=r"(r[11]),"=r"(r[12]),"=r"(r[13]),"=r"(r[14]),"=r"(r[15]),
          "=r"(r[16]),"=r"(r[17]),"=r"(r[18]),"=r"(r[19]),"=r"(r[20]),"=r"(r[21]),"=r"(r[22]),"=r"(r[23]),
          "=r"(r[24]),"=r"(r[25]),"=r"(r[26]),"=r"(r[27]),"=r"(r[28]),"=r"(r[29]),"=r"(r[30]),"=r"(r[31])
        : "r"(addr));
#endif
}

// ---------------------------------------------------------------------------
// Kernel 1: KNN (k=8) + gather/mean + build padded x rows (259 used cols)
// ---------------------------------------------------------------------------
#define PPB 256
#define SCH 2048

__global__ void __launch_bounds__(256) knn_build_x(
    const float* __restrict__ tmpl, const float* __restrict__ surf,
    const float* __restrict__ pfeat)
{
    __shared__ float4 ssurf[SCH];
    __shared__ int    sidx[PPB * KNN];

    const int b  = blockIdx.x / (TT / PPB);
    const int p0 = (blockIdx.x % (TT / PPB)) * PPB;
    const int tid = threadIdx.x;

    const int pt = p0 + tid;
    const size_t trow = ((size_t)b * TT + pt) * 3;
    const float tx = tmpl[trow + 0], ty = tmpl[trow + 1], tz = tmpl[trow + 2];
    const float tsq = tx * tx + ty * ty + tz * tz;
    const float ntx = -2.f * tx, nty = -2.f * ty, ntz = -2.f * tz;

    float bd[KNN]; int bi[KNN];
#pragma unroll
    for (int i = 0; i < KNN; i++) { bd[i] = 3.4e38f; bi[i] = 0; }
    float wmax = 3.4e38f; int wslot = 0;

    for (int c0 = 0; c0 < SSZ; c0 += SCH) {
        __syncthreads();
        for (int i = tid; i < SCH; i += 256) {
            size_t srow = ((size_t)b * SSZ + c0 + i) * 3;
            float sx = surf[srow], sy = surf[srow + 1], sz = surf[srow + 2];
            ssurf[i] = make_float4(sx, sy, sz, sx * sx + sy * sy + sz * sz);
        }
        __syncthreads();
#pragma unroll 4
        for (int s = 0; s < SCH; s++) {
            float4 v = ssurf[s];
            float d2 = fmaf(ntx, v.x, fmaf(nty, v.y, fmaf(ntz, v.z, tsq + v.w)));
            if (d2 < wmax) {
#pragma unroll
                for (int i = 0; i < KNN; i++)
                    if (i == wslot) { bd[i] = d2; bi[i] = c0 + s; }
                wmax = -1.f;
#pragma unroll
                for (int i = 0; i < KNN; i++)
                    if (bd[i] > wmax) { wmax = bd[i]; wslot = i; }
            }
        }
    }

#pragma unroll
    for (int i = 0; i < KNN; i++) sidx[tid * KNN + i] = bi[i];
    __syncthreads();

    const int lane = tid & 31, wid = tid >> 5;
    for (int q = 0; q < PPB / 8; q++) {
        const int lp = wid * (PPB / 8) + q;
        float acc[8];
#pragma unroll
        for (int j = 0; j < 8; j++) acc[j] = 0.f;
#pragma unroll
        for (int n = 0; n < KNN; n++) {
            const int sI = sidx[lp * KNN + n];
            const float* row = pfeat + ((size_t)b * SSZ + sI) * DD;
#pragma unroll
            for (int j = 0; j < 8; j++) acc[j] += row[lane + 32 * j];
        }
        const size_t xbase = ((size_t)b * TT + p0 + lp) * X_STRIDE;
#pragma unroll
        for (int j = 0; j < 8; j++)
            g_x[xbase + 3 + lane + 32 * j] = acc[j] * 0.125f;
        if (lane < 3)
            g_x[xbase + lane] = tmpl[((size_t)b * TT + p0 + lp) * 3 + lane];
        // zero pad cols 259..319
        g_x[xbase + KX + lane] = 0.f;
        if (lane < 29) g_x[xbase + KX + 32 + lane] = 0.f;
    }
}

// ---------------------------------------------------------------------------
// prep: repack all 4 weights (transposed bf16 hi/lo, K-padded) + fold the
// global-feature block of layer-1 weights into per-batch biases.
// ---------------------------------------------------------------------------
__global__ void __launch_bounds__(256) prep(
    const float* __restrict__ dw1, const float* __restrict__ dw2,
    const float* __restrict__ mw1, const float* __restrict__ mw2,
    const float* __restrict__ db1, const float* __restrict__ mb1,
    const float* __restrict__ gfeat)
{
    const int bid = blockIdx.x, tid = threadIdx.x;
    if (bid < 320) {                 // dw1: N=256, Kpad=320 (rows 0..258 used)
        int idx = bid * 256 + tid;
        int n = idx / 320, k = idx - n * 320;
        float v = (k < KX) ? dw1[(size_t)k * 256 + n] : 0.f;
        __nv_bfloat16 h = __float2bfloat16(v);
        g_dw1h[idx] = h;
        g_dw1l[idx] = __float2bfloat16(v - __bfloat162float(h));
    } else if (bid < 576) {          // dw2: 256x256
        int idx = (bid - 320) * 256 + tid;
        int n = idx >> 8, k = idx & 255;
        float v = dw2[(size_t)k * 256 + n];
        __nv_bfloat16 h = __float2bfloat16(v);
        g_dw2h[idx] = h;
        g_dw2l[idx] = __float2bfloat16(v - __bfloat162float(h));
    } else if (bid < 736) {          // mw1: N=128, Kpad=320
        int idx = (bid - 576) * 256 + tid;
        int n = idx / 320, k = idx - n * 320;
        float v = (k < KX) ? mw1[(size_t)k * 128 + n] : 0.f;
        __nv_bfloat16 h = __float2bfloat16(v);
        g_mw1h[idx] = h;
        g_mw1l[idx] = __float2bfloat16(v - __bfloat162float(h));
    } else if (bid < 768) {          // mw2: 64x128
        int idx = (bid - 736) * 256 + tid;
        int n = idx >> 7, k = idx & 127;
        float v = mw2[(size_t)k * 64 + n];
        __nv_bfloat16 h = __float2bfloat16(v);
        g_mw2h[idx] = h;
        g_mw2l[idx] = __float2bfloat16(v - __bfloat162float(h));
    } else if (bid < 772) {          // g_gbd[b][n] = db1[n] + gfeat[b] . dw1[259: ,n]
        int b = bid - 768;
        float s = db1[tid];
#pragma unroll 4
        for (int k = 0; k < GG; k++)
            s = fmaf(gfeat[b * GG + k], dw1[(size_t)(KX + k) * 256 + tid], s);
        g_gbd[b * 256 + tid] = s;
    } else {                         // g_gbm[b][n]
        int b = bid - 772;
        if (tid < 128) {
            float s = mb1[tid];
#pragma unroll 4
            for (int k = 0; k < GG; k++)
                s = fmaf(gfeat[b * GG + k], mw1[(size_t)(KX + k) * 128 + tid], s);
            g_gbm[b * 128 + tid] = s;
        }
    }
}

// ---------------------------------------------------------------------------
// tcgen05 GEMM, double-buffered: C = act(A[M,K] @ Bt^T + bias[batch])
// CTA: 128 rows x NT cols, K in chunks of 64 (4 K16-steps, 3 split-MMAs each)
// ---------------------------------------------------------------------------
template<int NT>
__global__ void __launch_bounds__(256) gemm_tc(
    const float* __restrict__ A, int Astride, int kchunks,
    const __nv_bfloat16* __restrict__ Bth, const __nv_bfloat16* __restrict__ Btl,
    int Kpad, const float* __restrict__ bias, int bstride,
    float* __restrict__ C, int relu)
{
#if TC_ENABLED
    extern __shared__ __align__(1024) char smem[];
    // A buf b: hi at b*32768, lo at b*32768+16384.  B base 65536, buf b at
    // 65536 + b*NT*256 (hi +0, lo +NT*128).
    __shared__ uint32_t s_tmem;
    __shared__ __align__(8) uint64_t s_mbar[2];
    __shared__ float sb[NT];

    const uint32_t smb = smem_u32(smem);
    const uint32_t mb0 = smem_u32(&s_mbar[0]);
    const int tid = threadIdx.x, wid = tid >> 5, lane = tid & 31;
    const int bm = blockIdx.x * 128;

    if (tid < NT) sb[tid] = bias[(bm >> 14) * bstride + tid];
    if (wid == 0) { TC_ALLOC(smem_u32(&s_tmem), NT); TC_RELINQ(); }
    if (tid == 0) { MBAR_INIT(mb0, 1); MBAR_INIT(mb0 + 8, 1); }
    __syncthreads();
    uint32_t tmem;
    asm volatile("ld.shared.b32 %0, [%1];" : "=r"(tmem) : "r"(smem_u32(&s_tmem)));

    const uint32_t idesc = (1u << 4) | (1u << 7) | (1u << 10) | ((NT / 8) << 17) | (8u << 24);

    uint32_t par[2] = {0u, 0u};
    for (int ch = 0; ch < kchunks; ch++) {
        const int bsel = ch & 1;
        if (ch >= 2) {               // buffer reuse: wait for MMA of ch-2
            mbar_wait(mb0 + bsel * 8, par[bsel]);
            par[bsel] ^= 1;
        }
        const uint32_t abase = (uint32_t)bsel * 32768u;
        const uint32_t bbase = 65536u + (uint32_t)bsel * ((uint32_t)NT * 256u);

        // stage A chunk: 128 rows x 64 fp32 -> bf16 hi/lo, SW128
        for (int u = tid; u < 1024; u += 256) {
            int r = u >> 3, c8 = u & 7;
            const float* src = A + (size_t)(bm + r) * Astride + (size_t)ch * 64 + c8 * 8;
            float4 v0 = *(const float4*)src;
            float4 v1 = *(const float4*)(src + 4);
            float a[8] = {v0.x, v0.y, v0.z, v0.w, v1.x, v1.y, v1.z, v1.w};
            __align__(16) __nv_bfloat16 h[8], l[8];
#pragma unroll
            for (int j = 0; j < 8; j++) {
                h[j] = __float2bfloat16(a[j]);
                l[j] = __float2bfloat16(a[j] - __bfloat162float(h[j]));
            }
            uint32_t off = SWZ128((uint32_t)(r * 128 + c8 * 16));
            *(uint4*)(smem + abase + off)         = *(const uint4*)h;
            *(uint4*)(smem + abase + 16384 + off) = *(const uint4*)l;
        }
        // stage B chunk: NT rows x 64 bf16 (hi/lo), SW128
        for (int u = tid; u < NT * 8; u += 256) {
            int r = u >> 3, c8 = u & 7;
            size_t g = (size_t)r * Kpad + (size_t)ch * 64 + c8 * 8;
            uint4 vh = *(const uint4*)(Bth + g);
            uint4 vl = *(const uint4*)(Btl + g);
            uint32_t off = SWZ128((uint32_t)(r * 128 + c8 * 16));
            *(uint4*)(smem + bbase + off)            = vh;
            *(uint4*)(smem + bbase + NT * 128 + off) = vl;
        }
        __syncthreads();

        if (wid == 0 && elect_one_pred()) {
            FENCE_ASYNC();
            uint64_t ah = MAKE_DESC(smb + abase), al = MAKE_DESC(smb + abase + 16384);
            uint64_t bh = MAKE_DESC(smb + bbase), bl = MAKE_DESC(smb + bbase + NT * 128);
#pragma unroll
            for (int ks = 0; ks < 4; ks++) {
                uint32_t en0 = (ch == 0 && ks == 0) ? 0u : 1u;
                mma_f16_ss(tmem, ah + ks * 2, bh + ks * 2, idesc, en0);
                mma_f16_ss(tmem, ah + ks * 2, bl + ks * 2, idesc, 1u);
                mma_f16_ss(tmem, al + ks * 2, bh + ks * 2, idesc, 1u);
            }
            TC_COMMIT(mb0 + bsel * 8);
        }
        // no trailing sync: next chunk stages the other buffer
    }

    { // wait for last chunk's commit (covers all prior MMAs)
        const int bl = (kchunks - 1) & 1;
        mbar_wait(mb0 + bl * 8, par[bl]);
    }
    TC_FENCE_AFTER();

    if (wid < 4) {
        const size_t row = bm + wid * 32 + lane;
#pragma unroll
        for (int c0 = 0; c0 < NT; c0 += 32) {
            uint32_t r[32];
            tc_ld_x32(r, tmem + c0);
            TC_WAIT_LD();
#pragma unroll
            for (int j4 = 0; j4 < 8; j4++) {
                float v0 = __uint_as_float(r[j4 * 4 + 0]) + sb[c0 + j4 * 4 + 0];
                float v1 = __uint_as_float(r[j4 * 4 + 1]) + sb[c0 + j4 * 4 + 1];
                float v2 = __uint_as_float(r[j4 * 4 + 2]) + sb[c0 + j4 * 4 + 2];
                float v3 = __uint_as_float(r[j4 * 4 + 3]) + sb[c0 + j4 * 4 + 3];
                if (relu) {
                    v0 = fmaxf(v0, 0.f); v1 = fmaxf(v1, 0.f);
                    v2 = fmaxf(v2, 0.f); v3 = fmaxf(v3, 0.f);
                }
                *(float4*)(C + row * NT + c0 + j4 * 4) = make_float4(v0, v1, v2, v3);
            }
        }
    }
    __syncthreads();
    if (wid == 0) TC_DEALLOC(tmem, NT);
#endif  // TC_ENABLED
}

// ---------------------------------------------------------------------------
// Head kernels
// ---------------------------------------------------------------------------
__global__ void __launch_bounds__(256) disp_head(
    const float* __restrict__ h2, const float* __restrict__ w,
    const float* __restrict__ b3, float* __restrict__ out)
{
    __shared__ float sw[256 * 3];
    const int tid = threadIdx.x;
    for (int i = tid; i < 768; i += 256) sw[i] = w[i];
    __syncthreads();
    const int lane = tid & 31, wid = tid >> 5;
    const int row = blockIdx.x * 8 + wid;
    const float* hr = h2 + (size_t)row * 256;
    float a0 = 0.f, a1 = 0.f, a2 = 0.f;
#pragma unroll
    for (int j = 0; j < 8; j++) {
        float h = hr[lane + 32 * j];
        a0 = fmaf(h, sw[(lane + 32 * j) * 3 + 0], a0);
        a1 = fmaf(h, sw[(lane + 32 * j) * 3 + 1], a1);
        a2 = fmaf(h, sw[(lane + 32 * j) * 3 + 2], a2);
    }
#pragma unroll
    for (int o = 16; o > 0; o >>= 1) {
        a0 += __shfl_down_sync(0xffffffffu, a0, o);
        a1 += __shfl_down_sync(0xffffffffu, a1, o);
        a2 += __shfl_down_sync(0xffffffffu, a2, o);
    }
    if (lane == 0) {
        out[(size_t)row * 3 + 0] = a0 + b3[0];
        out[(size_t)row * 3 + 1] = a1 + b3[1];
        out[(size_t)row * 3 + 2] = a2 + b3[2];
    }
}

__global__ void __launch_bounds__(256) mat_head(
    const float* __restrict__ m2, const float* __restrict__ w,
    const float* __restrict__ b, float* __restrict__ out)
{
    __shared__ float sw[64];
    const int tid = threadIdx.x;
    if (tid < 64) sw[tid] = w[tid];
    __syncthreads();
    const int lane = tid & 31, wid = tid >> 5;
    const int row = blockIdx.x * 8 + wid;
    const float* mr = m2 + (size_t)row * 64;
    float a = fmaf(mr[lane], sw[lane], mr[lane + 32] * sw[lane + 32]);
#pragma unroll
    for (int o = 16; o > 0; o >>= 1)
        a += __shfl_down_sync(0xffffffffu, a, o);
    if (lane == 0) {
        float z = a + b[0];
        out[row] = 1.f / (1.f + expf(-z));
    }
}

// ---------------------------------------------------------------------------
extern "C" void kernel_launch(void* const* d_in, const int* in_sizes, int n_in,
                              void* d_out, int out_size)
{
    const float* tmpl  = (const float*)d_in[0];
    const float* surf  = (const float*)d_in[1];
    const float* gfeat = (const float*)d_in[2];
    const float* pfeat = (const float*)d_in[3];
    const float* dw1 = (const float*)d_in[4];
    const float* db1 = (const float*)d_in[5];
    const float* dw2 = (const float*)d_in[6];
    const float* db2 = (const float*)d_in[7];
    const float* dw3 = (const float*)d_in[8];
    const float* db3 = (const float*)d_in[9];
    const float* mw1 = (const float*)d_in[10];
    const float* mb1 = (const float*)d_in[11];
    const float* mw2 = (const float*)d_in[12];
    const float* mb2 = (const float*)d_in[13];
    const float* mw3 = (const float*)d_in[14];
    const float* mb3 = (const float*)d_in[15];
    float* out = (float*)d_out;

    float *x, *h1, *h2, *m1, *m2, *gbd, *gbm;
    cudaGetSymbolAddress((void**)&x,  g_x);
    cudaGetSymbolAddress((void**)&h1, g_h1);
    cudaGetSymbolAddress((void**)&h2, g_h2);
    cudaGetSymbolAddress((void**)&m1, g_m1);
    cudaGetSymbolAddress((void**)&m2, g_m2);
    cudaGetSymbolAddress((void**)&gbd, g_gbd);
    cudaGetSymbolAddress((void**)&gbm, g_gbm);
    __nv_bfloat16 *dw1h, *dw1l, *dw2h, *dw2l, *mw1h, *mw1l, *mw2h, *mw2l;
    cudaGetSymbolAddress((void**)&dw1h, g_dw1h);
    cudaGetSymbolAddress((void**)&dw1l, g_dw1l);
    cudaGetSymbolAddress((void**)&dw2h, g_dw2h);
    cudaGetSymbolAddress((void**)&dw2l, g_dw2l);
    cudaGetSymbolAddress((void**)&mw1h, g_mw1h);
    cudaGetSymbolAddress((void**)&mw1l, g_mw1l);
    cudaGetSymbolAddress((void**)&mw2h, g_mw2h);
    cudaGetSymbolAddress((void**)&mw2l, g_mw2l);

    cudaFuncSetAttribute(gemm_tc<256>, cudaFuncAttributeMaxDynamicSharedMemorySize, 65536 + 2 * 256 * 256);
    cudaFuncSetAttribute(gemm_tc<128>, cudaFuncAttributeMaxDynamicSharedMemorySize, 65536 + 2 * 128 * 256);
    cudaFuncSetAttribute(gemm_tc<64>,  cudaFuncAttributeMaxDynamicSharedMemorySize, 65536 + 2 * 64 * 256);

    // Launch order chosen so ncu (-s 5 -c 1) profiles gemm_tc<256> (launch #6).
    knn_build_x<<<MM / PPB, 256>>>(tmpl, surf, pfeat);                          // 1
    prep<<<776, 256>>>(dw1, dw2, mw1, mw2, db1, mb1, gfeat);                    // 2
    gemm_tc<128><<<MM / 128, 256, 65536 + 2 * 128 * 256>>>(                     // 3
        x, X_STRIDE, 5, mw1h, mw1l, 320, gbm, 128, m1, 1);
    gemm_tc<64><<<MM / 128, 256, 65536 + 2 * 64 * 256>>>(                       // 4
        m1, 128, 2, mw2h, mw2l, 128, mb2, 0, m2, 1);
    mat_head<<<MM / 8, 256>>>(m2, mw3, mb3, out + (size_t)MM * 3);              // 5
    gemm_tc<256><<<MM / 128, 256, 65536 + 2 * 256 * 256>>>(                     // 6
        x, X_STRIDE, 5, dw1h, dw1l, 320, gbd, 256, h1, 1);
    gemm_tc<256><<<MM / 128, 256, 65536 + 2 * 256 * 256>>>(                     // 7
        h1, 256, 4, dw2h, dw2l, 256, db2, 0, h2, 1);
    disp_head<<<MM / 8, 256>>>(h2, dw3, db3, out);                              // 8
}